// round 5
// baseline (speedup 1.0000x reference)
#include <cuda_runtime.h>
#include <float.h>

// Problem constants
#define Bc   4
#define Lc   2
#define Pc   100
#define TPPc 64
#define Dc   768
#define Gc   10
#define Tc   (Pc * TPPc)   // 6400

typedef unsigned long long u64;

// Packed fp32x2 helpers (Blackwell sm_103a): two independent rn-FMAs per issue.
__device__ __forceinline__ void ffma2(u64& d, u64 a, u64 b) {
    asm("fma.rn.f32x2 %0, %1, %2, %0;" : "+l"(d) : "l"(a), "l"(b));
}
__device__ __forceinline__ void unpack2(u64 v, float& lo, float& hi) {
    asm("mov.b64 {%0, %1}, %2;" : "=f"(lo), "=f"(hi) : "l"(v));
}

// ---------------------------------------------------------------------------
// Scratch (static __device__ arrays; no allocation anywhere)
// ---------------------------------------------------------------------------
__device__ float g_WpEff[Bc * Dc * Dc];             // per-batch effective P-proj weight
__device__ float g_WtEff[Bc * Dc * Dc];             // per-batch effective T-proj weight
__device__ float g_M[Bc * Dc * Dc];                 // Wp_eff @ W1_top (fused)
__device__ float g_cp[Bc * Dc];                     // a @ Wp_a + b_p
__device__ float g_ct[Bc * Dc];                     // a @ Wt_a + b_t
__device__ float g_c1[Bc * Dc];                     // cp @ W1_top + b1
__device__ float g_TS[(size_t)Bc * Tc * Dc];        // ts (pre-segmax)
__device__ float g_Seg[Bc * Gc * TPPc * Dc];        // segment max over passages
__device__ float g_Agg[Bc * Gc * TPPc * Dc];        // SegMax @ W1_bot
__device__ float g_partial[(size_t)Bc * Tc * 6];    // per-row partial scores (6 N-tiles)
__device__ int   g_plist[Bc * Pc];                  // passages grouped by table id
__device__ int   g_goff[Bc * (Gc + 1)];             // group offsets into g_plist

// ---------------------------------------------------------------------------
// Per-batch effective weights: W_eff[k][n] = W[D+k][n] + a[k]*W[2D+k][n]
// ---------------------------------------------------------------------------
__global__ void prep_eff_k(const float* __restrict__ ans,
                           const float* __restrict__ Wp,
                           const float* __restrict__ Wt)
{
    const int k = blockIdx.x;
    const int b = blockIdx.y;
    const float ab = ans[(size_t)(b * Lc + (Lc - 1)) * Dc + k];
    const float* wpq = Wp + (size_t)(Dc + k) * Dc;
    const float* wpc = Wp + (size_t)(2 * Dc + k) * Dc;
    const float* wtq = Wt + (size_t)(Dc + k) * Dc;
    const float* wtc = Wt + (size_t)(2 * Dc + k) * Dc;
    float* op = g_WpEff + (size_t)b * Dc * Dc + (size_t)k * Dc;
    float* ot = g_WtEff + (size_t)b * Dc * Dc + (size_t)k * Dc;
#pragma unroll
    for (int m = 0; m < 3; m++) {
        const int n = m * 256 + threadIdx.x;
        op[n] = fmaf(ab, wpc[n], wpq[n]);
        ot[n] = fmaf(ab, wtc[n], wtq[n]);
    }
}

// ---------------------------------------------------------------------------
// GEMV: out[b][n] = sum_k x[b][k] * W[k][n] + bias[n]
//   mode 0: cp = a @ Wp[0:D] + b_p
//   mode 1: ct = a @ Wt[0:D] + b_t
//   mode 2: c1 = cp @ W1[0:D] + b1   (must run after mode 0)
// ---------------------------------------------------------------------------
__global__ void gemv_k(int mode,
                       const float* __restrict__ ans,
                       const float* __restrict__ Wp, const float* __restrict__ bp,
                       const float* __restrict__ Wt, const float* __restrict__ bt,
                       const float* __restrict__ W1, const float* __restrict__ b1)
{
    const int b = blockIdx.x;
    const float *x, *W, *bias;
    float* outv;
    if (mode == 0)      { x = ans + (size_t)(b * Lc + (Lc - 1)) * Dc; W = Wp; bias = bp; outv = g_cp + b * Dc; }
    else if (mode == 1) { x = ans + (size_t)(b * Lc + (Lc - 1)) * Dc; W = Wt; bias = bt; outv = g_ct + b * Dc; }
    else                { x = g_cp + b * Dc;                          W = W1; bias = b1; outv = g_c1 + b * Dc; }

    __shared__ float xs[Dc];
    for (int i = threadIdx.x; i < Dc; i += 256) xs[i] = x[i];
    __syncthreads();

    const int n = blockIdx.y * 256 + threadIdx.x;
    float acc = bias[n];
#pragma unroll 4
    for (int k = 0; k < Dc; k++)
        acc = fmaf(xs[k], W[(size_t)k * Dc + n], acc);
    outv[n] = acc;
}

// ---------------------------------------------------------------------------
// Group lists: passages bucketed by table id (tiny, serial per batch)
// ---------------------------------------------------------------------------
__global__ void build_groups_k(const int* __restrict__ tids)
{
    const int b = blockIdx.x;
    if (threadIdx.x != 0) return;
    int cnt[Gc];
    for (int g = 0; g < Gc; g++) cnt[g] = 0;
    for (int p = 0; p < Pc; p++) cnt[tids[b * Pc + p]]++;
    int off[Gc + 1];
    off[0] = 0;
    for (int g = 0; g < Gc; g++) off[g + 1] = off[g] + cnt[g];
    for (int g = 0; g <= Gc; g++) g_goff[b * (Gc + 1) + g] = off[g];
    int cur[Gc];
    for (int g = 0; g < Gc; g++) cur[g] = off[g];
    for (int p = 0; p < Pc; p++) {
        const int g = tids[b * Pc + p];
        g_plist[b * Pc + cur[g]++] = p;
    }
}

// ---------------------------------------------------------------------------
// Segment max over passages per (b, g, tpp, d). Deterministic (no atomics).
// ---------------------------------------------------------------------------
__global__ void segmax_k()
{
    const int tpp = blockIdx.x;
    const int g   = blockIdx.y;
    const int b   = blockIdx.z;
    const int s = g_goff[b * (Gc + 1) + g];
    const int e = g_goff[b * (Gc + 1) + g + 1];
#pragma unroll
    for (int m = 0; m < 3; m++) {
        const int d = m * 256 + threadIdx.x;
        float mv = -FLT_MAX;
        for (int i = s; i < e; i++) {
            const int p = g_plist[b * Pc + i];
            const float v = g_TS[((size_t)b * Tc + p * TPPc + tpp) * Dc + d];
            mv = fmaxf(mv, v);
        }
        g_Seg[(((size_t)(b * Gc + g) * TPPc) + tpp) * Dc + d] = (s < e) ? mv : 0.f;
    }
}

// ---------------------------------------------------------------------------
// SGEMM 128x128x8 tile, 256 threads, 8x8 per thread.
// - Inner loop fully packed f32x2; A tile LANE-DUPLICATED in smem so packed
//   A operands load directly as 64-bit words (zero repack MOVs).
// - Register prefetch + DOUBLE-BUFFERED smem: exactly ONE barrier per k-tile;
//   STS of tile t+1 goes to the idle buffer while tile t is computed.
//   mode 0: M      = Wp_eff @ W1_top                 (rows 768)
//   mode 1: TS     = q @ Wt_eff + ct     -> g_TS     (rows 6400)
//   mode 2: Agg    = SegMax @ W1_bot                 (rows 640)
//   mode 3: main   = q @ M, epilogue: +c1 +Agg[g] -> relu -> ·W2 -> row partial
// ---------------------------------------------------------------------------
__global__ __launch_bounds__(256, 2)
void sgemm_k(int mode, const float* __restrict__ q, const float* __restrict__ W1,
             const float* __restrict__ W2, const int* __restrict__ tids)
{
    const int b = blockIdx.z;
    const float* A;
    const float* Bm;
    if (mode == 0)      { A = g_WpEff + (size_t)b * Dc * Dc;                 Bm = W1; }
    else if (mode == 1) { A = q + (size_t)(b * Lc + (Lc - 1)) * Tc * Dc;     Bm = g_WtEff + (size_t)b * Dc * Dc; }
    else if (mode == 2) { A = g_Seg + (size_t)b * Gc * TPPc * Dc;            Bm = W1 + Dc * Dc; }
    else                { A = q + (size_t)(b * Lc + (Lc - 1)) * Tc * Dc;     Bm = g_M + (size_t)b * Dc * Dc; }

    const int rowBase = blockIdx.y * 128;
    const int colBase = blockIdx.x * 128;
    const int tid = threadIdx.x;
    const int tx = tid & 15;
    const int ty = tid >> 4;

    __shared__ float As2[2][8][256];   // duplicated pairs: [buf][k][2*row+{0,1}]
    __shared__ float Bs[2][8][128];

    // Accumulators: 8 rows x 4 packed col-pairs (= 8x8 scalar)
    u64 acc2[8][4];
#pragma unroll
    for (int i = 0; i < 8; i++)
#pragma unroll
        for (int j = 0; j < 4; j++) acc2[i][j] = 0ull;

    const int aRow = tid >> 1;
    const int aCol = (tid & 1) * 4;
    const int bRow = tid >> 5;
    const int bCol = (tid & 31) * 4;

    const float* aPtr = A + (size_t)(rowBase + aRow) * Dc + aCol;
    const float* bPtr = Bm + (size_t)bRow * Dc + colBase + bCol;

    // Prologue: tile 0 -> regs -> smem buf 0
    float4 av = *(const float4*)(aPtr);
    float4 bv = *(const float4*)(bPtr);
    As2[0][aCol + 0][2 * aRow] = av.x;  As2[0][aCol + 0][2 * aRow + 1] = av.x;
    As2[0][aCol + 1][2 * aRow] = av.y;  As2[0][aCol + 1][2 * aRow + 1] = av.y;
    As2[0][aCol + 2][2 * aRow] = av.z;  As2[0][aCol + 2][2 * aRow + 1] = av.z;
    As2[0][aCol + 3][2 * aRow] = av.w;  As2[0][aCol + 3][2 * aRow + 1] = av.w;
    *(float4*)&Bs[0][bRow][bCol] = bv;
    __syncthreads();

    int buf = 0;
    for (int k0 = 0; k0 < Dc; k0 += 8) {
        const bool more = (k0 + 8 < Dc);
        // Fetch next tile into registers; completes during compute below.
        if (more) {
            av = *(const float4*)(aPtr + k0 + 8);
            bv = *(const float4*)(bPtr + (size_t)(k0 + 8) * Dc);
        }

#pragma unroll
        for (int kk = 0; kk < 8; kk++) {
            u64 ra2[8], rb2[4];
            const u64* ap2 = (const u64*)&As2[buf][kk][ty * 16];   // 64B-aligned
            ra2[0] = ap2[0]; ra2[1] = ap2[1]; ra2[2] = ap2[2]; ra2[3] = ap2[3];
            ra2[4] = ap2[4]; ra2[5] = ap2[5]; ra2[6] = ap2[6]; ra2[7] = ap2[7];
            const u64* bp2 = (const u64*)&Bs[buf][kk][tx * 8];     // 32B-aligned
            rb2[0] = bp2[0]; rb2[1] = bp2[1]; rb2[2] = bp2[2]; rb2[3] = bp2[3];
#pragma unroll
            for (int i = 0; i < 8; i++) {
                ffma2(acc2[i][0], ra2[i], rb2[0]);
                ffma2(acc2[i][1], ra2[i], rb2[1]);
                ffma2(acc2[i][2], ra2[i], rb2[2]);
                ffma2(acc2[i][3], ra2[i], rb2[3]);
            }
        }

        if (more) {
            const int nb = buf ^ 1;   // idle buffer; prev readers drained by last BAR
            As2[nb][aCol + 0][2 * aRow] = av.x;  As2[nb][aCol + 0][2 * aRow + 1] = av.x;
            As2[nb][aCol + 1][2 * aRow] = av.y;  As2[nb][aCol + 1][2 * aRow + 1] = av.y;
            As2[nb][aCol + 2][2 * aRow] = av.z;  As2[nb][aCol + 2][2 * aRow + 1] = av.z;
            As2[nb][aCol + 3][2 * aRow] = av.w;  As2[nb][aCol + 3][2 * aRow + 1] = av.w;
            *(float4*)&Bs[nb][bRow][bCol] = bv;
            __syncthreads();          // publish nb; also drains readers of buf
            buf = nb;
        }
    }

    // Unpack accumulators to scalars for the epilogues
    float acc[8][8];
#pragma unroll
    for (int i = 0; i < 8; i++)
#pragma unroll
        for (int j = 0; j < 4; j++)
            unpack2(acc2[i][j], acc[i][2 * j], acc[i][2 * j + 1]);

    const int c0 = colBase + tx * 8;

    if (mode == 0 || mode == 2) {
        float* Cp = (mode == 0) ? (g_M + (size_t)b * Dc * Dc)
                                : (g_Agg + (size_t)b * Gc * TPPc * Dc);
#pragma unroll
        for (int i = 0; i < 8; i++) {
            float* dst = Cp + (size_t)(rowBase + ty * 8 + i) * Dc + c0;
            *(float4*)dst       = make_float4(acc[i][0], acc[i][1], acc[i][2], acc[i][3]);
            *(float4*)(dst + 4) = make_float4(acc[i][4], acc[i][5], acc[i][6], acc[i][7]);
        }
    } else if (mode == 1) {
        const float* ctb = g_ct + b * Dc + c0;
        float cv[8];
        *(float4*)&cv[0] = *(const float4*)ctb;
        *(float4*)&cv[4] = *(const float4*)(ctb + 4);
        float* Cp = g_TS + (size_t)b * Tc * Dc;
#pragma unroll
        for (int i = 0; i < 8; i++) {
            float* dst = Cp + (size_t)(rowBase + ty * 8 + i) * Dc + c0;
            *(float4*)dst       = make_float4(acc[i][0] + cv[0], acc[i][1] + cv[1],
                                              acc[i][2] + cv[2], acc[i][3] + cv[3]);
            *(float4*)(dst + 4) = make_float4(acc[i][4] + cv[4], acc[i][5] + cv[5],
                                              acc[i][6] + cv[6], acc[i][7] + cv[7]);
        }
    } else {
        float cv[8], wv[8];
        const float* c1b = g_c1 + b * Dc + c0;
        *(float4*)&cv[0] = *(const float4*)c1b;
        *(float4*)&cv[4] = *(const float4*)(c1b + 4);
        *(float4*)&wv[0] = *(const float4*)(W2 + c0);
        *(float4*)&wv[4] = *(const float4*)(W2 + c0 + 4);
#pragma unroll
        for (int i = 0; i < 8; i++) {
            const int row = rowBase + ty * 8 + i;
            const int p   = row >> 6;
            const int tpp = row & 63;
            const int g   = tids[b * Pc + p];
            const float* ag = g_Agg + ((size_t)(b * Gc + g) * TPPc + tpp) * Dc + c0;
            float agv[8];
            *(float4*)&agv[0] = *(const float4*)ag;
            *(float4*)&agv[4] = *(const float4*)(ag + 4);
            float rs = 0.f;
#pragma unroll
            for (int j = 0; j < 8; j++) {
                float h = acc[i][j] + cv[j] + agv[j];
                h = fmaxf(h, 0.f);
                rs = fmaf(h, wv[j], rs);
            }
            // reduce across the 16 tx lanes sharing this row
            rs += __shfl_xor_sync(0xffffffffu, rs, 1);
            rs += __shfl_xor_sync(0xffffffffu, rs, 2);
            rs += __shfl_xor_sync(0xffffffffu, rs, 4);
            rs += __shfl_xor_sync(0xffffffffu, rs, 8);
            if (tx == 0)
                g_partial[((size_t)b * Tc + row) * 6 + blockIdx.x] = rs;
        }
    }
}

// ---------------------------------------------------------------------------
// Final: out[b,p] = sum_tpp mask * (score + b2)
// ---------------------------------------------------------------------------
__global__ void finalize_k(const float* __restrict__ masks,
                           const float* __restrict__ b2,
                           float* __restrict__ out)
{
    const int bp = blockIdx.x;
    const int b = bp / Pc;
    const int p = bp % Pc;
    const int tpp = threadIdx.x;   // 64 threads
    const size_t row = (size_t)b * Tc + p * TPPc + tpp;
    float hs = 0.f;
#pragma unroll
    for (int nt = 0; nt < 6; nt++) hs += g_partial[row * 6 + nt];
    float v = masks[((size_t)b * Pc + p) * TPPc + tpp] * (hs + b2[0]);
#pragma unroll
    for (int o = 16; o > 0; o >>= 1) v += __shfl_xor_sync(0xffffffffu, v, o);
    __shared__ float sh[2];
    if ((threadIdx.x & 31) == 0) sh[threadIdx.x >> 5] = v;
    __syncthreads();
    if (threadIdx.x == 0) out[bp] = sh[0] + sh[1];
}

// ---------------------------------------------------------------------------
// Launch
// ---------------------------------------------------------------------------
extern "C" void kernel_launch(void* const* d_in, const int* in_sizes, int n_in,
                              void* d_out, int out_size)
{
    const float* ans   = (const float*)d_in[0];   // (B, L, 1, D)
    const float* q     = (const float*)d_in[1];   // (B, L, T, D)
    const float* masks = (const float*)d_in[2];   // (B, P, TPP)
    const int*   tids  = (const int*)  d_in[3];   // (B, P)
    // d_in[4] = fusion_scores (unused by reference)
    const float* Wp = (const float*)d_in[5];      // (3D, D)
    const float* bp = (const float*)d_in[6];      // (D)
    const float* Wt = (const float*)d_in[7];      // (3D, D)
    const float* bt = (const float*)d_in[8];      // (D)
    const float* W1 = (const float*)d_in[9];      // (2D, D)
    const float* b1 = (const float*)d_in[10];     // (D)
    const float* W2 = (const float*)d_in[11];     // (D, 1)
    const float* b2 = (const float*)d_in[12];     // (1)
    float* out = (float*)d_out;                   // (B, P)

    // 1. per-batch effective weights
    prep_eff_k<<<dim3(Dc, Bc), 256>>>(ans, Wp, Wt);
    // 2. constant vectors
    gemv_k<<<dim3(Bc, 3), 256>>>(0, ans, Wp, bp, Wt, bt, W1, b1);
    gemv_k<<<dim3(Bc, 3), 256>>>(1, ans, Wp, bp, Wt, bt, W1, b1);
    gemv_k<<<dim3(Bc, 3), 256>>>(2, ans, Wp, bp, Wt, bt, W1, b1);
    // 3. fused M = Wp_eff @ W1_top     (768 rows)
    sgemm_k<<<dim3(6, 6, Bc), 256>>>(0, q, W1, W2, tids);
    // 4. TS = q @ Wt_eff + ct          (6400 rows)
    sgemm_k<<<dim3(6, 50, Bc), 256>>>(1, q, W1, W2, tids);
    // 5. group lists + segment max
    build_groups_k<<<Bc, 32>>>(tids);
    segmax_k<<<dim3(TPPc, Gc, Bc), 256>>>();
    // 6. Agg = SegMax @ W1_bot         (640 rows)
    sgemm_k<<<dim3(6, 5, Bc), 256>>>(2, q, W1, W2, tids);
    // 7. main GEMM + fused relu/W2 epilogue
    sgemm_k<<<dim3(6, 50, Bc), 256>>>(3, q, W1, W2, tids);
    // 8. masked per-passage reduction
    finalize_k<<<Bc * Pc, 64>>>(masks, b2, out);
}

// round 7
// speedup vs baseline: 1.1696x; 1.1696x over previous
#include <cuda_runtime.h>
#include <float.h>

// Problem constants
#define Bc   4
#define Lc   2
#define Pc   100
#define TPPc 64
#define Dc   768
#define Gc   10
#define Tc   (Pc * TPPc)   // 6400

typedef unsigned long long u64;

// Packed fp32x2 helpers (Blackwell sm_103a): two independent rn-FMAs per issue.
__device__ __forceinline__ void ffma2(u64& d, u64 a, u64 b) {
    asm("fma.rn.f32x2 %0, %1, %2, %0;" : "+l"(d) : "l"(a), "l"(b));
}
__device__ __forceinline__ void unpack2(u64 v, float& lo, float& hi) {
    asm("mov.b64 {%0, %1}, %2;" : "=f"(lo), "=f"(hi) : "l"(v));
}

// ---------------------------------------------------------------------------
// Scratch (static __device__ arrays; no allocation anywhere)
// ---------------------------------------------------------------------------
__device__ float g_WpEff[Bc * Dc * Dc];             // per-batch effective P-proj weight
__device__ float g_WtEff[Bc * Dc * Dc];             // per-batch effective T-proj weight
__device__ float g_M[Bc * Dc * Dc];                 // Wp_eff @ W1_top (fused)
__device__ float g_cp[Bc * Dc];                     // a @ Wp_a + b_p
__device__ float g_ct[Bc * Dc];                     // a @ Wt_a + b_t
__device__ float g_c1[Bc * Dc];                     // cp @ W1_top + b1
__device__ float g_TS[(size_t)Bc * Tc * Dc];        // ts (pre-segmax)
__device__ float g_Seg[Bc * Gc * TPPc * Dc];        // segment max over passages
__device__ float g_Agg[Bc * Gc * TPPc * Dc];        // SegMax @ W1_bot
__device__ float g_partial[(size_t)Bc * Tc * 6];    // per-row partial scores (6 N-tiles)
__device__ int   g_plist[Bc * Pc];                  // passages grouped by table id
__device__ int   g_goff[Bc * (Gc + 1)];             // group offsets into g_plist

// ---------------------------------------------------------------------------
// Per-batch effective weights: W_eff[k][n] = W[D+k][n] + a[k]*W[2D+k][n]
// ---------------------------------------------------------------------------
__global__ void prep_eff_k(const float* __restrict__ ans,
                           const float* __restrict__ Wp,
                           const float* __restrict__ Wt)
{
    const int k = blockIdx.x;
    const int b = blockIdx.y;
    const float ab = ans[(size_t)(b * Lc + (Lc - 1)) * Dc + k];
    const float* wpq = Wp + (size_t)(Dc + k) * Dc;
    const float* wpc = Wp + (size_t)(2 * Dc + k) * Dc;
    const float* wtq = Wt + (size_t)(Dc + k) * Dc;
    const float* wtc = Wt + (size_t)(2 * Dc + k) * Dc;
    float* op = g_WpEff + (size_t)b * Dc * Dc + (size_t)k * Dc;
    float* ot = g_WtEff + (size_t)b * Dc * Dc + (size_t)k * Dc;
#pragma unroll
    for (int m = 0; m < 3; m++) {
        const int n = m * 256 + threadIdx.x;
        op[n] = fmaf(ab, wpc[n], wpq[n]);
        ot[n] = fmaf(ab, wtc[n], wtq[n]);
    }
}

// ---------------------------------------------------------------------------
// Parallel GEMV for cp and ct (+ build_groups piggybacked on y==12):
//   z=0: cp = a @ Wp[0:D] + b_p       z=1: ct = a @ Wt[0:D] + b_t
// Block: 256 threads = 64 outputs x 4 K-parts (192 each), 8 indep accs,
// coalesced warp loads (32 consecutive n per warp), smem reduce.
// ---------------------------------------------------------------------------
__global__ void gemv01_k(const float* __restrict__ ans,
                         const float* __restrict__ Wp, const float* __restrict__ bpv,
                         const float* __restrict__ Wt, const float* __restrict__ btv,
                         const int* __restrict__ tids)
{
    const int b = blockIdx.x;

    if (blockIdx.y == 12) {                      // build_groups slot
        if (blockIdx.z == 0 && threadIdx.x == 0) {
            int cnt[Gc];
            for (int g = 0; g < Gc; g++) cnt[g] = 0;
            for (int p = 0; p < Pc; p++) cnt[tids[b * Pc + p]]++;
            int off[Gc + 1];
            off[0] = 0;
            for (int g = 0; g < Gc; g++) off[g + 1] = off[g] + cnt[g];
            for (int g = 0; g <= Gc; g++) g_goff[b * (Gc + 1) + g] = off[g];
            int cur[Gc];
            for (int g = 0; g < Gc; g++) cur[g] = off[g];
            for (int p = 0; p < Pc; p++) {
                const int g = tids[b * Pc + p];
                g_plist[b * Pc + cur[g]++] = p;
            }
        }
        return;
    }

    const float* W    = (blockIdx.z == 0) ? Wp  : Wt;
    const float* bias = (blockIdx.z == 0) ? bpv : btv;
    float* outv       = ((blockIdx.z == 0) ? g_cp : g_ct) + b * Dc;
    const float* x    = ans + (size_t)(b * Lc + (Lc - 1)) * Dc;

    __shared__ float xs[Dc];
    __shared__ float red[4][64];
    for (int i = threadIdx.x; i < Dc; i += 256) xs[i] = x[i];
    __syncthreads();

    const int nl = threadIdx.x & 63;
    const int kp = threadIdx.x >> 6;
    const int n  = blockIdx.y * 64 + nl;
    const int k0 = kp * 192;

    float a0 = 0.f, a1 = 0.f, a2 = 0.f, a3 = 0.f,
          a4 = 0.f, a5 = 0.f, a6 = 0.f, a7 = 0.f;
#pragma unroll 4
    for (int kk = 0; kk < 192; kk += 8) {
        const int k = k0 + kk;
        a0 = fmaf(xs[k + 0], W[(size_t)(k + 0) * Dc + n], a0);
        a1 = fmaf(xs[k + 1], W[(size_t)(k + 1) * Dc + n], a1);
        a2 = fmaf(xs[k + 2], W[(size_t)(k + 2) * Dc + n], a2);
        a3 = fmaf(xs[k + 3], W[(size_t)(k + 3) * Dc + n], a3);
        a4 = fmaf(xs[k + 4], W[(size_t)(k + 4) * Dc + n], a4);
        a5 = fmaf(xs[k + 5], W[(size_t)(k + 5) * Dc + n], a5);
        a6 = fmaf(xs[k + 6], W[(size_t)(k + 6) * Dc + n], a6);
        a7 = fmaf(xs[k + 7], W[(size_t)(k + 7) * Dc + n], a7);
    }
    red[kp][nl] = ((a0 + a1) + (a2 + a3)) + ((a4 + a5) + (a6 + a7));
    __syncthreads();
    if (kp == 0)
        outv[n] = ((red[0][nl] + red[1][nl]) + (red[2][nl] + red[3][nl])) + bias[n];
}

// ---------------------------------------------------------------------------
// Segment max over passages per (b, g, tpp, d). Deterministic (no atomics).
// ---------------------------------------------------------------------------
__global__ void segmax_k()
{
    const int tpp = blockIdx.x;
    const int g   = blockIdx.y;
    const int b   = blockIdx.z;
    const int s = g_goff[b * (Gc + 1) + g];
    const int e = g_goff[b * (Gc + 1) + g + 1];
#pragma unroll
    for (int m = 0; m < 3; m++) {
        const int d = m * 256 + threadIdx.x;
        float mv = -FLT_MAX;
        for (int i = s; i < e; i++) {
            const int p = g_plist[b * Pc + i];
            const float v = g_TS[((size_t)b * Tc + p * TPPc + tpp) * Dc + d];
            mv = fmaxf(mv, v);
        }
        g_Seg[(((size_t)(b * Gc + g) * TPPc) + tpp) * Dc + d] = (s < e) ? mv : 0.f;
    }
}

// ---------------------------------------------------------------------------
// SGEMM 128x128x8 tile, 256 threads, 8x8 per thread.
// - Packed f32x2 inner loop; A tile LANE-DUPLICATED in smem (zero repack MOVs);
//   operand loads via LDS.128 (6 LDS/kk instead of 12).
// - Register prefetch + double-buffered smem: one barrier per k-tile.
//   mode 4 (merged launch): y<50 -> mode1 rows, y in [50,56) -> mode0 rows,
//                           y==56 -> c1 = cp @ W1_top + b1 GEMV.
//   mode 2: Agg = SegMax @ W1_bot   mode 3: main GEMM + fused epilogue
// ---------------------------------------------------------------------------
__global__ __launch_bounds__(256, 2)
void sgemm_k(int mode, const float* __restrict__ q, const float* __restrict__ W1,
             const float* __restrict__ W2, const int* __restrict__ tids,
             const float* __restrict__ b1v)
{
    const int b = blockIdx.z;
    const int tid = threadIdx.x;

    __shared__ float As2[2][8][256];   // duplicated pairs: [buf][k][2*row+{0,1}]
    __shared__ float Bs[2][8][128];

    int mode_eff = mode;
    int yTile = blockIdx.y;
    if (mode == 4) {
        if (blockIdx.y < 50)       { mode_eff = 1; yTile = blockIdx.y; }
        else if (blockIdx.y < 56)  { mode_eff = 0; yTile = blockIdx.y - 50; }
        else {
            // ---- c1 GEMV: c1[b][n] = sum_k cp[b][k]*W1[k][n] + b1[n] ----
            float* xs  = &As2[0][0][0];        // 768 floats scratch
            float* red = xs + Dc;              // 256 floats scratch
            const float* x = g_cp + b * Dc;
            for (int i = tid; i < Dc; i += 256) xs[i] = x[i];
            __syncthreads();
            const int nl = tid & 127;
            const int kp = tid >> 7;           // 0..1, 384 K each
            const int n  = blockIdx.x * 128 + nl;
            const int k0 = kp * 384;
            float a0 = 0.f, a1 = 0.f, a2 = 0.f, a3 = 0.f,
                  a4 = 0.f, a5 = 0.f, a6 = 0.f, a7 = 0.f;
#pragma unroll 4
            for (int kk = 0; kk < 384; kk += 8) {
                const int k = k0 + kk;
                a0 = fmaf(xs[k + 0], W1[(size_t)(k + 0) * Dc + n], a0);
                a1 = fmaf(xs[k + 1], W1[(size_t)(k + 1) * Dc + n], a1);
                a2 = fmaf(xs[k + 2], W1[(size_t)(k + 2) * Dc + n], a2);
                a3 = fmaf(xs[k + 3], W1[(size_t)(k + 3) * Dc + n], a3);
                a4 = fmaf(xs[k + 4], W1[(size_t)(k + 4) * Dc + n], a4);
                a5 = fmaf(xs[k + 5], W1[(size_t)(k + 5) * Dc + n], a5);
                a6 = fmaf(xs[k + 6], W1[(size_t)(k + 6) * Dc + n], a6);
                a7 = fmaf(xs[k + 7], W1[(size_t)(k + 7) * Dc + n], a7);
            }
            red[kp * 128 + nl] = ((a0 + a1) + (a2 + a3)) + ((a4 + a5) + (a6 + a7));
            __syncthreads();
            if (kp == 0)
                g_c1[b * Dc + n] = (red[nl] + red[128 + nl]) + b1v[n];
            return;
        }
    }

    const float* A;
    const float* Bm;
    if (mode_eff == 0)      { A = g_WpEff + (size_t)b * Dc * Dc;               Bm = W1; }
    else if (mode_eff == 1) { A = q + (size_t)(b * Lc + (Lc - 1)) * Tc * Dc;   Bm = g_WtEff + (size_t)b * Dc * Dc; }
    else if (mode_eff == 2) { A = g_Seg + (size_t)b * Gc * TPPc * Dc;          Bm = W1 + Dc * Dc; }
    else                    { A = q + (size_t)(b * Lc + (Lc - 1)) * Tc * Dc;   Bm = g_M + (size_t)b * Dc * Dc; }

    const int rowBase = yTile * 128;
    const int colBase = blockIdx.x * 128;
    const int tx = tid & 15;
    const int ty = tid >> 4;

    // Accumulators: 8 rows x 4 packed col-pairs (= 8x8 scalar)
    u64 acc2[8][4];
#pragma unroll
    for (int i = 0; i < 8; i++)
#pragma unroll
        for (int j = 0; j < 4; j++) acc2[i][j] = 0ull;

    const int aRow = tid >> 1;
    const int aCol = (tid & 1) * 4;
    const int bRow = tid >> 5;
    const int bCol = (tid & 31) * 4;

    const float* aPtr = A + (size_t)(rowBase + aRow) * Dc + aCol;
    const float* bPtr = Bm + (size_t)bRow * Dc + colBase + bCol;

    // Prologue: tile 0 -> regs -> smem buf 0
    float4 av = *(const float4*)(aPtr);
    float4 bv = *(const float4*)(bPtr);
    As2[0][aCol + 0][2 * aRow] = av.x;  As2[0][aCol + 0][2 * aRow + 1] = av.x;
    As2[0][aCol + 1][2 * aRow] = av.y;  As2[0][aCol + 1][2 * aRow + 1] = av.y;
    As2[0][aCol + 2][2 * aRow] = av.z;  As2[0][aCol + 2][2 * aRow + 1] = av.z;
    As2[0][aCol + 3][2 * aRow] = av.w;  As2[0][aCol + 3][2 * aRow + 1] = av.w;
    *(float4*)&Bs[0][bRow][bCol] = bv;
    __syncthreads();

    int buf = 0;
    for (int k0 = 0; k0 < Dc; k0 += 8) {
        const bool more = (k0 + 8 < Dc);
        // Fetch next tile into registers; completes during compute below.
        if (more) {
            av = *(const float4*)(aPtr + k0 + 8);
            bv = *(const float4*)(bPtr + (size_t)(k0 + 8) * Dc);
        }

#pragma unroll
        for (int kk = 0; kk < 8; kk++) {
            u64 ra2[8], rb2[4];
            const ulonglong2* ap4 = (const ulonglong2*)&As2[buf][kk][ty * 16];  // 64B-aligned
            ulonglong2 t0 = ap4[0], t1 = ap4[1], t2 = ap4[2], t3 = ap4[3];
            ra2[0] = t0.x; ra2[1] = t0.y; ra2[2] = t1.x; ra2[3] = t1.y;
            ra2[4] = t2.x; ra2[5] = t2.y; ra2[6] = t3.x; ra2[7] = t3.y;
            const ulonglong2* bp4 = (const ulonglong2*)&Bs[buf][kk][tx * 8];    // 32B-aligned
            ulonglong2 s0 = bp4[0], s1 = bp4[1];
            rb2[0] = s0.x; rb2[1] = s0.y; rb2[2] = s1.x; rb2[3] = s1.y;
#pragma unroll
            for (int i = 0; i < 8; i++) {
                ffma2(acc2[i][0], ra2[i], rb2[0]);
                ffma2(acc2[i][1], ra2[i], rb2[1]);
                ffma2(acc2[i][2], ra2[i], rb2[2]);
                ffma2(acc2[i][3], ra2[i], rb2[3]);
            }
        }

        if (more) {
            const int nb = buf ^ 1;   // idle buffer; prev readers drained by last BAR
            As2[nb][aCol + 0][2 * aRow] = av.x;  As2[nb][aCol + 0][2 * aRow + 1] = av.x;
            As2[nb][aCol + 1][2 * aRow] = av.y;  As2[nb][aCol + 1][2 * aRow + 1] = av.y;
            As2[nb][aCol + 2][2 * aRow] = av.z;  As2[nb][aCol + 2][2 * aRow + 1] = av.z;
            As2[nb][aCol + 3][2 * aRow] = av.w;  As2[nb][aCol + 3][2 * aRow + 1] = av.w;
            *(float4*)&Bs[nb][bRow][bCol] = bv;
            __syncthreads();          // publish nb; also drains readers of buf
            buf = nb;
        }
    }

    // Unpack accumulators to scalars for the epilogues
    float acc[8][8];
#pragma unroll
    for (int i = 0; i < 8; i++)
#pragma unroll
        for (int j = 0; j < 4; j++)
            unpack2(acc2[i][j], acc[i][2 * j], acc[i][2 * j + 1]);

    const int c0 = colBase + tx * 8;

    if (mode_eff == 0 || mode_eff == 2) {
        float* Cp = (mode_eff == 0) ? (g_M + (size_t)b * Dc * Dc)
                                    : (g_Agg + (size_t)b * Gc * TPPc * Dc);
#pragma unroll
        for (int i = 0; i < 8; i++) {
            float* dst = Cp + (size_t)(rowBase + ty * 8 + i) * Dc + c0;
            *(float4*)dst       = make_float4(acc[i][0], acc[i][1], acc[i][2], acc[i][3]);
            *(float4*)(dst + 4) = make_float4(acc[i][4], acc[i][5], acc[i][6], acc[i][7]);
        }
    } else if (mode_eff == 1) {
        const float* ctb = g_ct + b * Dc + c0;
        float cv[8];
        *(float4*)&cv[0] = *(const float4*)ctb;
        *(float4*)&cv[4] = *(const float4*)(ctb + 4);
        float* Cp = g_TS + (size_t)b * Tc * Dc;
#pragma unroll
        for (int i = 0; i < 8; i++) {
            float* dst = Cp + (size_t)(rowBase + ty * 8 + i) * Dc + c0;
            *(float4*)dst       = make_float4(acc[i][0] + cv[0], acc[i][1] + cv[1],
                                              acc[i][2] + cv[2], acc[i][3] + cv[3]);
            *(float4*)(dst + 4) = make_float4(acc[i][4] + cv[4], acc[i][5] + cv[5],
                                              acc[i][6] + cv[6], acc[i][7] + cv[7]);
        }
    } else {
        float cv[8], wv[8];
        const float* c1b = g_c1 + b * Dc + c0;
        *(float4*)&cv[0] = *(const float4*)c1b;
        *(float4*)&cv[4] = *(const float4*)(c1b + 4);
        *(float4*)&wv[0] = *(const float4*)(W2 + c0);
        *(float4*)&wv[4] = *(const float4*)(W2 + c0 + 4);
#pragma unroll
        for (int i = 0; i < 8; i++) {
            const int row = rowBase + ty * 8 + i;
            const int p   = row >> 6;
            const int tpp = row & 63;
            const int g   = tids[b * Pc + p];
            const float* ag = g_Agg + ((size_t)(b * Gc + g) * TPPc + tpp) * Dc + c0;
            float agv[8];
            *(float4*)&agv[0] = *(const float4*)ag;
            *(float4*)&agv[4] = *(const float4*)(ag + 4);
            float rs = 0.f;
#pragma unroll
            for (int j = 0; j < 8; j++) {
                float h = acc[i][j] + cv[j] + agv[j];
                h = fmaxf(h, 0.f);
                rs = fmaf(h, wv[j], rs);
            }
            // reduce across the 16 tx lanes sharing this row
            rs += __shfl_xor_sync(0xffffffffu, rs, 1);
            rs += __shfl_xor_sync(0xffffffffu, rs, 2);
            rs += __shfl_xor_sync(0xffffffffu, rs, 4);
            rs += __shfl_xor_sync(0xffffffffu, rs, 8);
            if (tx == 0)
                g_partial[((size_t)b * Tc + row) * 6 + blockIdx.x] = rs;
        }
    }
}

// ---------------------------------------------------------------------------
// Final: out[b,p] = sum_tpp mask * (score + b2)
// ---------------------------------------------------------------------------
__global__ void finalize_k(const float* __restrict__ masks,
                           const float* __restrict__ b2,
                           float* __restrict__ out)
{
    const int bp = blockIdx.x;
    const int b = bp / Pc;
    const int p = bp % Pc;
    const int tpp = threadIdx.x;   // 64 threads
    const size_t row = (size_t)b * Tc + p * TPPc + tpp;
    float hs = 0.f;
#pragma unroll
    for (int nt = 0; nt < 6; nt++) hs += g_partial[row * 6 + nt];
    float v = masks[((size_t)b * Pc + p) * TPPc + tpp] * (hs + b2[0]);
#pragma unroll
    for (int o = 16; o > 0; o >>= 1) v += __shfl_xor_sync(0xffffffffu, v, o);
    __shared__ float sh[2];
    if ((threadIdx.x & 31) == 0) sh[threadIdx.x >> 5] = v;
    __syncthreads();
    if (threadIdx.x == 0) out[bp] = sh[0] + sh[1];
}

// ---------------------------------------------------------------------------
// Launch
// ---------------------------------------------------------------------------
extern "C" void kernel_launch(void* const* d_in, const int* in_sizes, int n_in,
                              void* d_out, int out_size)
{
    const float* ans   = (const float*)d_in[0];   // (B, L, 1, D)
    const float* q     = (const float*)d_in[1];   // (B, L, T, D)
    const float* masks = (const float*)d_in[2];   // (B, P, TPP)
    const int*   tids  = (const int*)  d_in[3];   // (B, P)
    // d_in[4] = fusion_scores (unused by reference)
    const float* Wp = (const float*)d_in[5];      // (3D, D)
    const float* bp = (const float*)d_in[6];      // (D)
    const float* Wt = (const float*)d_in[7];      // (3D, D)
    const float* bt = (const float*)d_in[8];      // (D)
    const float* W1 = (const float*)d_in[9];      // (2D, D)
    const float* b1 = (const float*)d_in[10];     // (D)
    const float* W2 = (const float*)d_in[11];     // (D, 1)
    const float* b2 = (const float*)d_in[12];     // (1)
    float* out = (float*)d_out;                   // (B, P)

    // 1. per-batch effective weights
    prep_eff_k<<<dim3(Dc, Bc), 256>>>(ans, Wp, Wt);
    // 2. cp & ct GEMVs (parallel K-split) + build_groups piggyback
    gemv01_k<<<dim3(Bc, 13, 2), 256>>>(ans, Wp, bp, Wt, bt, tids);
    // 3. merged: TS GEMM (y<50) + M GEMM (50<=y<56) + c1 GEMV (y==56)
    sgemm_k<<<dim3(6, 57, Bc), 256>>>(4, q, W1, W2, tids, b1);
    // 4. segment max
    segmax_k<<<dim3(TPPc, Gc, Bc), 256>>>();
    // 5. Agg = SegMax @ W1_bot
    sgemm_k<<<dim3(6, 5, Bc), 256>>>(2, q, W1, W2, tids, b1);
    // 6. main GEMM + fused relu/W2 epilogue
    sgemm_k<<<dim3(6, 50, Bc), 256>>>(3, q, W1, W2, tids, b1);
    // 7. masked per-passage reduction
    finalize_k<<<Bc * Pc, 64>>>(masks, b2, out);
}